// round 10
// baseline (speedup 1.0000x reference)
#include <cuda_runtime.h>
#include <cuda_fp8.h>
#include <cstdint>

// ============================================================================
// ContrastiveLoss (N=4096, D=256, tau=0.1)
//   z = normalize(concat(x1,x2)) * sqrt(10*log2(e)) -> e4m3   (scale folded in)
//   acc = z'_r . z'_j = 14.427 * sim  ->  exp(sim/tau) = ex2(acc)
//   denom[r] = sum_j exp(...)  (diag -> exp(0)=1);  pos in exact fp32
// Triangle fused FP8 mma.sync GEMM, 128x32 tiles, warp tile 16x32.
// ROUND 10: split epilogue — phase1 (ex2+fold) right after acc ready, then
// issue tile t+1's MMAs (acc reused), then phase2 (shuffle tree + atomics)
// overlapping the in-flight MMAs. Hides the serial SHFL/atomic latency.
// ============================================================================

static constexpr int NROWS = 4096;
static constexpr int TWO_N = 8192;
static constexpr int D     = 256;          // K
static constexpr int BM    = 128;          // rows per strip
static constexpr int BN    = 32;           // cols per tile
// pair p in [0,32): strip p (256-4p tiles) + strip 63-p (4p+4 tiles) = 260.
static constexpr int NUM_TILES = 8320;
static constexpr int NUM_CTAS  = 296;                // 2 per SM
static constexpr int K_STEPS   = D / 32;             // 8 (fp8 k=32 per mma)
static constexpr int NTHREADS  = 256;

// sqrt(10 * log2(e)) — folded into z so epilogue is a bare ex2
#define ZSCALE 3.79828214f

// SMEM: padded row stride 272 B (17 x 16B)
static constexpr int TSTRIDE_B = 272;
static constexpr int A_TILE_BYTES = BM * TSTRIDE_B;   // 34816
static constexpr int B_TILE_BYTES = BN * TSTRIDE_B;   // 8704
static constexpr int SMEM_TOTAL = A_TILE_BYTES + 3 * B_TILE_BYTES;  // 60928

// ---------------- device scratch (allocation-free) --------------------------
__device__ unsigned char g_z8[TWO_N * D];   // e4m3 (pre-scaled), [8192][256]
__device__ float    g_pos[NROWS];
__device__ float    g_denom[TWO_N];
__device__ unsigned g_done;

// ---------------- PTX helpers ----------------------------------------------
__device__ __forceinline__ uint32_t smem_to_u32(const void* p) {
    uint32_t a;
    asm("{ .reg .u64 t; cvta.to.shared.u64 t, %1; cvt.u32.u64 %0, t; }"
        : "=r"(a) : "l"(p));
    return a;
}

__device__ __forceinline__ void cp_async16(uint32_t dst, const void* src) {
    asm volatile("cp.async.cg.shared.global [%0], [%1], 16;"
                 :: "r"(dst), "l"(src) : "memory");
}
#define CP_COMMIT() asm volatile("cp.async.commit_group;" ::: "memory")
#define CP_WAIT1()  asm volatile("cp.async.wait_group 1;" ::: "memory")

__device__ __forceinline__ void ldsm_x4(uint32_t* r, uint32_t addr) {
    asm volatile("ldmatrix.sync.aligned.m8n8.x4.shared.b16 {%0,%1,%2,%3}, [%4];"
                 : "=r"(r[0]), "=r"(r[1]), "=r"(r[2]), "=r"(r[3]) : "r"(addr));
}

#define MMA16832F8(d, a, bx, by) \
    asm volatile( \
        "mma.sync.aligned.m16n8k32.row.col.f32.e4m3.e4m3.f32 " \
        "{%0,%1,%2,%3}, {%4,%5,%6,%7}, {%8,%9}, {%0,%1,%2,%3};" \
        : "+f"((d)[0]), "+f"((d)[1]), "+f"((d)[2]), "+f"((d)[3]) \
        : "r"((a)[0]), "r"((a)[1]), "r"((a)[2]), "r"((a)[3]), \
          "r"(bx), "r"(by))

__device__ __forceinline__ float ex2f(float x) {
    float r;
    asm("ex2.approx.ftz.f32 %0, %1;" : "=f"(r) : "f"(x));
    return r;
}

__device__ __forceinline__ uint32_t pack_e4m3x4(float v0, float v1, float v2, float v3) {
    __nv_fp8x2_storage_t lo =
        __nv_cvt_float2_to_fp8x2(make_float2(v0, v1), __NV_SATFINITE, __NV_E4M3);
    __nv_fp8x2_storage_t hi =
        __nv_cvt_float2_to_fp8x2(make_float2(v2, v3), __NV_SATFINITE, __NV_E4M3);
    return (uint32_t)lo | ((uint32_t)hi << 16);
}

// ---------------- Stage 1: fused normalize + pos (reads x1/x2 once) --------
__global__ void normpos_kernel(const float* __restrict__ x1, const float* __restrict__ x2) {
    int i    = blockIdx.x * 8 + (threadIdx.x >> 5);   // pair row 0..4095
    int lane = threadIdx.x & 31;
    if (blockIdx.x == 0 && threadIdx.x == 0) g_done = 0;

    const float4* s1 = reinterpret_cast<const float4*>(x1 + (size_t)i * D);
    const float4* s2 = reinterpret_cast<const float4*>(x2 + (size_t)i * D);
    float4 a0 = s1[lane * 2], a1 = s1[lane * 2 + 1];
    float4 b0 = s2[lane * 2], b1 = s2[lane * 2 + 1];

    float ss1 = a0.x * a0.x + a0.y * a0.y + a0.z * a0.z + a0.w * a0.w
              + a1.x * a1.x + a1.y * a1.y + a1.z * a1.z + a1.w * a1.w;
    float ss2 = b0.x * b0.x + b0.y * b0.y + b0.z * b0.z + b0.w * b0.w
              + b1.x * b1.x + b1.y * b1.y + b1.z * b1.z + b1.w * b1.w;
    float dot = a0.x * b0.x + a0.y * b0.y + a0.z * b0.z + a0.w * b0.w
              + a1.x * b1.x + a1.y * b1.y + a1.z * b1.z + a1.w * b1.w;
    #pragma unroll
    for (int o = 16; o; o >>= 1) {
        ss1 += __shfl_xor_sync(0xffffffffu, ss1, o);
        ss2 += __shfl_xor_sync(0xffffffffu, ss2, o);
        dot += __shfl_xor_sync(0xffffffffu, dot, o);
    }
    float inv1 = 1.0f / fmaxf(sqrtf(ss1), 1e-12f);
    float inv2 = 1.0f / fmaxf(sqrtf(ss2), 1e-12f);
    if (lane == 0) {
        g_pos[i] = dot * inv1 * inv2;     // exact fp32, unscaled
        g_denom[i] = 0.0f;
        g_denom[i + NROWS] = 0.0f;
    }
    float q1 = inv1 * ZSCALE, q2 = inv2 * ZSCALE;

    uint2 w1, w2;
    w1.x = pack_e4m3x4(a0.x * q1, a0.y * q1, a0.z * q1, a0.w * q1);
    w1.y = pack_e4m3x4(a1.x * q1, a1.y * q1, a1.z * q1, a1.w * q1);
    w2.x = pack_e4m3x4(b0.x * q2, b0.y * q2, b0.z * q2, b0.w * q2);
    w2.y = pack_e4m3x4(b1.x * q2, b1.y * q2, b1.z * q2, b1.w * q2);
    *reinterpret_cast<uint2*>(g_z8 + (size_t)i * D + lane * 8) = w1;
    *reinterpret_cast<uint2*>(g_z8 + (size_t)(i + NROWS) * D + lane * 8) = w2;
}

// ---------------- tile loaders (fp8 rows of 256 B) ---------------------------
__device__ __forceinline__ void load_A(uint32_t dst, int row0, int tid) {
    const unsigned char* src = g_z8 + (size_t)row0 * D;
    #pragma unroll
    for (int i = 0; i < 8; i++) {
        int idx = tid + i * NTHREADS;      // 2048 chunks of 16B
        int r = idx >> 4, s = idx & 15;
        cp_async16(dst + r * TSTRIDE_B + s * 16, src + r * D + s * 16);
    }
}
__device__ __forceinline__ void load_B(uint32_t dst, int row0, int tid) {
    const unsigned char* src = g_z8 + (size_t)row0 * D;
    #pragma unroll
    for (int i = 0; i < 2; i++) {
        int idx = tid + i * NTHREADS;      // 512 chunks of 16B
        int r = idx >> 4, s = idx & 15;
        cp_async16(dst + r * TSTRIDE_B + s * 16, src + r * D + s * 16);
    }
}

// MMA for one 16x32 warp tile: zero acc, 8 ksteps of ldsm + 4 MMAs
__device__ __forceinline__ void mma_tile(float (&acc)[4][4], uint32_t Ab, uint32_t Bb) {
    #pragma unroll
    for (int ni = 0; ni < 4; ni++)
        #pragma unroll
        for (int e = 0; e < 4; e++) acc[ni][e] = 0.0f;
    #pragma unroll
    for (int ks = 0; ks < K_STEPS; ks++) {
        uint32_t a[4], b01[4], b23[4];
        ldsm_x4(a,   Ab + ks * 32);
        ldsm_x4(b01, Bb + ks * 32);
        ldsm_x4(b23, Bb + 16 * TSTRIDE_B + ks * 32);
        MMA16832F8(acc[0], a, b01[0], b01[2]);
        MMA16832F8(acc[1], a, b01[1], b01[3]);
        MMA16832F8(acc[2], a, b23[0], b23[2]);
        MMA16832F8(acc[3], a, b23[1], b23[3]);
    }
}

// ---------------- Stage 2: triangular fused FP8 GEMM + ex2 + sums -----------
__global__ __launch_bounds__(NTHREADS, 2)
void gemm_kernel(float* __restrict__ out) {
    extern __shared__ char smem[];
    const int tid  = threadIdx.x;
    const int lane = tid & 31;
    const int warp = tid >> 5;              // 0..7, owns rows warp*16..+16
    const int cta  = blockIdx.x;

    const uint32_t smem_u = smem_to_u32(smem);
    const uint32_t A_base = smem_u;
    const uint32_t Bb0 = smem_u + A_TILE_BYTES;

    const int t0 = (int)(((long long)cta * NUM_TILES) / NUM_CTAS);
    const int t1 = (int)(((long long)(cta + 1) * NUM_TILES) / NUM_CTAS);

    const uint32_t a_off = (uint32_t)((warp * 16 + (lane & 15)) * TSTRIDE_B
                                      + (lane >> 4) * 16);
    const uint32_t b_off = (uint32_t)((lane & 15) * TSTRIDE_B + (lane >> 4) * 16);

    float denom[2] = {0, 0};                // rows warp*16 + d*8 + lane>>2
    float acc[4][4];
    float cs[8];

    int t = t0;
    while (t < t1) {
        // decode segment: contiguous run of tiles sharing strip I
        int p   = t / 260;
        int idx = t - p * 260;
        int na  = 256 - 4 * p;
        int I, J, seg_end;
        if (idx < na) { I = p;      J = 4 * p + idx;             seg_end = 260 * p + na; }
        else          { I = 63 - p; J = 252 - 4 * p + (idx - na); seg_end = 260 * (p + 1); }
        const int te = (seg_end < t1) ? seg_end : t1;

        // ---- segment prologue: A + B(t), B(t+1); first tile's MMA ----
        load_A(A_base, I * BM, tid);
        load_B(Bb0 + (t % 3) * B_TILE_BYTES, J * BN, tid);
        CP_COMMIT();                                   // G: A + B(t)
        if (t + 1 < te)
            load_B(Bb0 + ((t + 1) % 3) * B_TILE_BYTES, (J + 1) * BN, tid);
        CP_COMMIT();                                   // G: B(t+1) (maybe empty)
        CP_WAIT1();                                    // A + B(t) landed
        __syncthreads();
        mma_tile(acc, A_base + a_off, Bb0 + (t % 3) * B_TILE_BYTES + b_off);

        const int row0 = I * BM + warp * 16;

        for (; t < te; t++, J++) {
            // prefetch B(t+2)
            if (t + 2 < te)
                load_B(Bb0 + ((t + 2) % 3) * B_TILE_BYTES, (J + 2) * BN, tid);
            CP_COMMIT();                               // maybe empty group

            // ---- phase 1: ex2 + row sums + in-thread column fold (tile t) ----
            const int col0 = J * BN;
            const bool diagblk = ((J >> 2) == I);
            if (diagblk) {
                #pragma unroll
                for (int ni = 0; ni < 4; ni++)
                    #pragma unroll
                    for (int e = 0; e < 4; e++) {
                        float v = ex2f(acc[ni][e]);
                        int r = row0 + (e >> 1) * 8 + (lane >> 2);
                        int c = col0 + ni * 8 + (lane & 3) * 2 + (e & 1);
                        if (c == r) v = 1.0f;          // diag -> exp(0)
                        denom[e >> 1] += v;
                    }
            } else {
                #pragma unroll
                for (int ni = 0; ni < 4; ni++) {
                    float v0 = ex2f(acc[ni][0]);
                    float v1 = ex2f(acc[ni][1]);
                    float v2 = ex2f(acc[ni][2]);
                    float v3 = ex2f(acc[ni][3]);
                    denom[0] += v0 + v1;
                    denom[1] += v2 + v3;
                    cs[ni * 2]     = v0 + v2;          // col ni*8 + (lane&3)*2
                    cs[ni * 2 + 1] = v1 + v3;          // col ni*8 + (lane&3)*2+1
                }
            }

            // ---- issue next tile's MMA (acc dead after phase 1) ----
            if (t + 1 < te) {
                CP_WAIT1();                            // B(t+1) landed
                __syncthreads();
                mma_tile(acc, A_base + a_off,
                         Bb0 + ((t + 1) % 3) * B_TILE_BYTES + b_off);
            }

            // ---- phase 2: shuffle tree + atomics, overlapped with MMAs ----
            if (!diagblk) {
                #pragma unroll
                for (int k = 0; k < 8; k++) {
                    float x = cs[k];
                    x += __shfl_xor_sync(0xffffffffu, x, 4);
                    x += __shfl_xor_sync(0xffffffffu, x, 8);
                    x += __shfl_xor_sync(0xffffffffu, x, 16);
                    cs[k] = x;
                }
                if (lane < 4) {
                    #pragma unroll
                    for (int k = 0; k < 8; k++)
                        atomicAdd(&g_denom[col0 + (k >> 1) * 8 + lane * 2 + (k & 1)],
                                  cs[k]);
                }
            }
        }

        // segment epilogue: flush row denominators, protect A/B for next segment
        #pragma unroll
        for (int d = 0; d < 2; d++) {
            denom[d] += __shfl_xor_sync(0xffffffffu, denom[d], 1);
            denom[d] += __shfl_xor_sync(0xffffffffu, denom[d], 2);
        }
        if ((lane & 3) == 0) {
            #pragma unroll
            for (int d = 0; d < 2; d++)
                atomicAdd(&g_denom[row0 + d * 8 + (lane >> 2)], denom[d]);
        }
        denom[0] = denom[1] = 0.0f;
        __syncthreads();                     // all reads of A/B done before reload
    }

    // ---- last CTA: final log/mean reduction ----
    __threadfence();
    __shared__ unsigned s_tick;
    if (tid == 0) s_tick = atomicAdd(&g_done, 1u);
    __syncthreads();
    if (s_tick == NUM_CTAS - 1) {
        float s = 0.0f;
        for (int r = tid; r < TWO_N; r += NTHREADS)
            s += logf(g_denom[r]) - g_pos[r & (NROWS - 1)] * 10.0f;
        #pragma unroll
        for (int o = 16; o; o >>= 1) s += __shfl_xor_sync(0xffffffffu, s, o);
        __shared__ float red[8];
        if (lane == 0) red[warp] = s;
        __syncthreads();
        if (tid == 0) {
            float v = 0.0f;
            #pragma unroll
            for (int w = 0; w < 8; w++) v += red[w];
            out[0] = v * (1.0f / (float)TWO_N);
        }
    }
}

// ---------------- launch ----------------------------------------------------
extern "C" void kernel_launch(void* const* d_in, const int* in_sizes, int n_in,
                              void* d_out, int out_size) {
    (void)in_sizes; (void)n_in; (void)out_size;
    const float* x1 = (const float*)d_in[0];
    const float* x2 = (const float*)d_in[1];
    float* out = (float*)d_out;

    cudaFuncSetAttribute(gemm_kernel,
                         cudaFuncAttributeMaxDynamicSharedMemorySize, SMEM_TOTAL);

    normpos_kernel<<<NROWS / 8, 256>>>(x1, x2);
    gemm_kernel<<<NUM_CTAS, NTHREADS, SMEM_TOTAL>>>(out);
}

// round 11
// speedup vs baseline: 1.0477x; 1.0477x over previous
#include <cuda_runtime.h>
#include <cuda_fp8.h>
#include <cstdint>

// ============================================================================
// ContrastiveLoss (N=4096, D=256, tau=0.1)
//   z = normalize(concat(x1,x2)) * sqrt(10*log2(e)) -> e4m3   (scale folded in)
//   acc = z'_r . z'_j = 14.427 * sim  ->  exp(sim/tau) = ex2(acc)
//   denom[r] = sum_j exp(...)  (diag -> exp(0)=1);  pos in exact fp32
// ROUND 11: single persistent kernel. Phase A: normalize+pos (warp/row).
// Device-wide spin barrier (all 296 CTAs co-resident at 2/SM). Phase B:
// round-9 triangular fused FP8 mma.sync GEMM loop (the 79.1us best).
// ============================================================================

static constexpr int NROWS = 4096;
static constexpr int TWO_N = 8192;
static constexpr int D     = 256;          // K
static constexpr int BM    = 128;          // rows per strip
static constexpr int BN    = 32;           // cols per tile
// pair p in [0,32): strip p (256-4p tiles) + strip 63-p (4p+4 tiles) = 260.
static constexpr int NUM_TILES = 8320;
static constexpr int NUM_CTAS  = 296;                // 2 per SM, all resident
static constexpr int K_STEPS   = D / 32;             // 8 (fp8 k=32 per mma)
static constexpr int NTHREADS  = 256;
static constexpr int NWARPS_G  = NUM_CTAS * (NTHREADS / 32);   // 2368

// sqrt(10 * log2(e)) — folded into z so epilogue is a bare ex2
#define ZSCALE 3.79828214f

// SMEM: padded row stride 272 B (17 x 16B)
static constexpr int TSTRIDE_B = 272;
static constexpr int A_TILE_BYTES = BM * TSTRIDE_B;   // 34816
static constexpr int B_TILE_BYTES = BN * TSTRIDE_B;   // 8704
static constexpr int SMEM_TOTAL = A_TILE_BYTES + 3 * B_TILE_BYTES;  // 60928

// ---------------- device scratch (allocation-free) --------------------------
__device__ unsigned char g_z8[TWO_N * D];   // e4m3 (pre-scaled), [8192][256]
__device__ float    g_pos[NROWS];
__device__ float    g_denom[TWO_N];
__device__ unsigned g_sync = 0;             // phase barrier (reset by last CTA)
__device__ unsigned g_done = 0;             // completion ticket (reset by last CTA)

// ---------------- PTX helpers ----------------------------------------------
__device__ __forceinline__ uint32_t smem_to_u32(const void* p) {
    uint32_t a;
    asm("{ .reg .u64 t; cvta.to.shared.u64 t, %1; cvt.u32.u64 %0, t; }"
        : "=r"(a) : "l"(p));
    return a;
}

__device__ __forceinline__ void cp_async16(uint32_t dst, const void* src) {
    asm volatile("cp.async.cg.shared.global [%0], [%1], 16;"
                 :: "r"(dst), "l"(src) : "memory");
}
#define CP_COMMIT() asm volatile("cp.async.commit_group;" ::: "memory")
#define CP_WAIT1()  asm volatile("cp.async.wait_group 1;" ::: "memory")

__device__ __forceinline__ void ldsm_x4(uint32_t* r, uint32_t addr) {
    asm volatile("ldmatrix.sync.aligned.m8n8.x4.shared.b16 {%0,%1,%2,%3}, [%4];"
                 : "=r"(r[0]), "=r"(r[1]), "=r"(r[2]), "=r"(r[3]) : "r"(addr));
}

#define MMA16832F8(d, a, bx, by) \
    asm volatile( \
        "mma.sync.aligned.m16n8k32.row.col.f32.e4m3.e4m3.f32 " \
        "{%0,%1,%2,%3}, {%4,%5,%6,%7}, {%8,%9}, {%0,%1,%2,%3};" \
        : "+f"((d)[0]), "+f"((d)[1]), "+f"((d)[2]), "+f"((d)[3]) \
        : "r"((a)[0]), "r"((a)[1]), "r"((a)[2]), "r"((a)[3]), \
          "r"(bx), "r"(by))

__device__ __forceinline__ float ex2f(float x) {
    float r;
    asm("ex2.approx.ftz.f32 %0, %1;" : "=f"(r) : "f"(x));
    return r;
}

__device__ __forceinline__ uint32_t pack_e4m3x4(float v0, float v1, float v2, float v3) {
    __nv_fp8x2_storage_t lo =
        __nv_cvt_float2_to_fp8x2(make_float2(v0, v1), __NV_SATFINITE, __NV_E4M3);
    __nv_fp8x2_storage_t hi =
        __nv_cvt_float2_to_fp8x2(make_float2(v2, v3), __NV_SATFINITE, __NV_E4M3);
    return (uint32_t)lo | ((uint32_t)hi << 16);
}

// ---------------- tile loaders (fp8 rows of 256 B) ---------------------------
__device__ __forceinline__ void load_A(uint32_t dst, int row0, int tid) {
    const unsigned char* src = g_z8 + (size_t)row0 * D;
    #pragma unroll
    for (int i = 0; i < 8; i++) {
        int idx = tid + i * NTHREADS;      // 2048 chunks of 16B
        int r = idx >> 4, s = idx & 15;
        cp_async16(dst + r * TSTRIDE_B + s * 16, src + r * D + s * 16);
    }
}
__device__ __forceinline__ void load_B(uint32_t dst, int row0, int tid) {
    const unsigned char* src = g_z8 + (size_t)row0 * D;
    #pragma unroll
    for (int i = 0; i < 2; i++) {
        int idx = tid + i * NTHREADS;      // 512 chunks of 16B
        int r = idx >> 4, s = idx & 15;
        cp_async16(dst + r * TSTRIDE_B + s * 16, src + r * D + s * 16);
    }
}

// ---------------- the single persistent kernel ------------------------------
__global__ __launch_bounds__(NTHREADS, 2)
void fused_kernel(const float* __restrict__ x1, const float* __restrict__ x2,
                  float* __restrict__ out) {
    extern __shared__ char smem[];
    const int tid  = threadIdx.x;
    const int lane = tid & 31;
    const int warp = tid >> 5;              // 0..7
    const int cta  = blockIdx.x;

    // ======== Phase A: normalize + pos for this CTA's rows ========
    const int gw = cta * 8 + warp;          // global warp id, 0..2367
    for (int i = gw; i < NROWS; i += NWARPS_G) {
        const float4* s1 = reinterpret_cast<const float4*>(x1 + (size_t)i * D);
        const float4* s2 = reinterpret_cast<const float4*>(x2 + (size_t)i * D);
        float4 a0 = s1[lane * 2], a1 = s1[lane * 2 + 1];
        float4 b0 = s2[lane * 2], b1 = s2[lane * 2 + 1];

        float ss1 = a0.x * a0.x + a0.y * a0.y + a0.z * a0.z + a0.w * a0.w
                  + a1.x * a1.x + a1.y * a1.y + a1.z * a1.z + a1.w * a1.w;
        float ss2 = b0.x * b0.x + b0.y * b0.y + b0.z * b0.z + b0.w * b0.w
                  + b1.x * b1.x + b1.y * b1.y + b1.z * b1.z + b1.w * b1.w;
        float dot = a0.x * b0.x + a0.y * b0.y + a0.z * b0.z + a0.w * b0.w
                  + a1.x * b1.x + a1.y * b1.y + a1.z * b1.z + a1.w * b1.w;
        #pragma unroll
        for (int o = 16; o; o >>= 1) {
            ss1 += __shfl_xor_sync(0xffffffffu, ss1, o);
            ss2 += __shfl_xor_sync(0xffffffffu, ss2, o);
            dot += __shfl_xor_sync(0xffffffffu, dot, o);
        }
        float inv1 = 1.0f / fmaxf(sqrtf(ss1), 1e-12f);
        float inv2 = 1.0f / fmaxf(sqrtf(ss2), 1e-12f);
        if (lane == 0) {
            g_pos[i] = dot * inv1 * inv2;   // exact fp32, unscaled
            g_denom[i] = 0.0f;
            g_denom[i + NROWS] = 0.0f;
        }
        float q1 = inv1 * ZSCALE, q2 = inv2 * ZSCALE;

        uint2 w1, w2;
        w1.x = pack_e4m3x4(a0.x * q1, a0.y * q1, a0.z * q1, a0.w * q1);
        w1.y = pack_e4m3x4(a1.x * q1, a1.y * q1, a1.z * q1, a1.w * q1);
        w2.x = pack_e4m3x4(b0.x * q2, b0.y * q2, b0.z * q2, b0.w * q2);
        w2.y = pack_e4m3x4(b1.x * q2, b1.y * q2, b1.z * q2, b1.w * q2);
        *reinterpret_cast<uint2*>(g_z8 + (size_t)i * D + lane * 8) = w1;
        *reinterpret_cast<uint2*>(g_z8 + (size_t)(i + NROWS) * D + lane * 8) = w2;
    }

    // ======== device-wide barrier (all 296 CTAs resident at 2/SM) ========
    __syncthreads();
    if (tid == 0) {
        __threadfence();
        atomicAdd(&g_sync, 1u);
        while (*(volatile unsigned*)&g_sync < NUM_CTAS) { }
        __threadfence();
    }
    __syncthreads();

    // ======== Phase B: triangular fused FP8 GEMM + ex2 + sums (R9 loop) ======
    const uint32_t smem_u = smem_to_u32(smem);
    const uint32_t A_base = smem_u;
    const uint32_t Bb0 = smem_u + A_TILE_BYTES;

    const int t0 = (int)(((long long)cta * NUM_TILES) / NUM_CTAS);
    const int t1 = (int)(((long long)(cta + 1) * NUM_TILES) / NUM_CTAS);

    const uint32_t a_off = (uint32_t)((warp * 16 + (lane & 15)) * TSTRIDE_B
                                      + (lane >> 4) * 16);
    const uint32_t b_off = (uint32_t)((lane & 15) * TSTRIDE_B + (lane >> 4) * 16);

    float denom[2] = {0, 0};                // rows warp*16 + d*8 + lane>>2

    int t = t0;
    while (t < t1) {
        // decode segment: contiguous run of tiles sharing strip I
        int p   = t / 260;
        int idx = t - p * 260;
        int na  = 256 - 4 * p;
        int I, J, seg_end;
        if (idx < na) { I = p;      J = 4 * p + idx;             seg_end = 260 * p + na; }
        else          { I = 63 - p; J = 252 - 4 * p + (idx - na); seg_end = 260 * (p + 1); }
        const int te = (seg_end < t1) ? seg_end : t1;

        // segment prologue: A strip + first B tile (one group)
        load_A(A_base, I * BM, tid);
        load_B(Bb0 + (t % 3) * B_TILE_BYTES, J * BN, tid);
        CP_COMMIT();

        const int row0 = I * BM + warp * 16;

        for (; t < te; t++, J++) {
            if (t + 1 < te)
                load_B(Bb0 + ((t + 1) % 3) * B_TILE_BYTES, (J + 1) * BN, tid);
            CP_COMMIT();                     // possibly empty group
            CP_WAIT1();                      // retire group for tile t (and A)
            __syncthreads();                 // single barrier per tile

            const uint32_t Ab = A_base + a_off;
            const uint32_t Bb = Bb0 + (t % 3) * B_TILE_BYTES + b_off;

            float acc[4][4];
            #pragma unroll
            for (int ni = 0; ni < 4; ni++)
                #pragma unroll
                for (int e = 0; e < 4; e++) acc[ni][e] = 0.0f;

            #pragma unroll
            for (int ks = 0; ks < K_STEPS; ks++) {
                uint32_t a[4], b01[4], b23[4];
                ldsm_x4(a,   Ab + ks * 32);
                ldsm_x4(b01, Bb + ks * 32);
                ldsm_x4(b23, Bb + 16 * TSTRIDE_B + ks * 32);
                MMA16832F8(acc[0], a, b01[0], b01[2]);
                MMA16832F8(acc[1], a, b01[1], b01[3]);
                MMA16832F8(acc[2], a, b23[0], b23[2]);
                MMA16832F8(acc[3], a, b23[1], b23[3]);
            }

            // epilogue: v = ex2(acc) = exp(sim/tau); acc reused for col sums
            const int col0 = J * BN;
            if ((J >> 2) == I) {             // diagonal block: row sums only
                #pragma unroll
                for (int ni = 0; ni < 4; ni++)
                    #pragma unroll
                    for (int e = 0; e < 4; e++) {
                        float v = ex2f(acc[ni][e]);
                        int r = row0 + (e >> 1) * 8 + (lane >> 2);
                        int c = col0 + ni * 8 + (lane & 3) * 2 + (e & 1);
                        if (c == r) v = 1.0f;            // diag -> exp(0)
                        denom[e >> 1] += v;
                    }
            } else {                         // off-diag: row sums + col sums
                #pragma unroll
                for (int ni = 0; ni < 4; ni++) {
                    #pragma unroll
                    for (int e = 0; e < 4; e++) {
                        float v = ex2f(acc[ni][e]);
                        denom[e >> 1] += v;
                        acc[ni][e] = v;      // keep for column reduction
                    }
                    acc[ni][0] += acc[ni][2];
                    acc[ni][1] += acc[ni][3];
                }
                #pragma unroll
                for (int ni = 0; ni < 4; ni++)
                    #pragma unroll
                    for (int h = 0; h < 2; h++) {
                        float x = acc[ni][h];
                        x += __shfl_xor_sync(0xffffffffu, x, 4);
                        x += __shfl_xor_sync(0xffffffffu, x, 8);
                        x += __shfl_xor_sync(0xffffffffu, x, 16);
                        acc[ni][h] = x;
                    }
                if (lane < 4) {
                    #pragma unroll
                    for (int ni = 0; ni < 4; ni++)
                        #pragma unroll
                        for (int h = 0; h < 2; h++)
                            atomicAdd(&g_denom[col0 + ni * 8 + lane * 2 + h],
                                      acc[ni][h]);
                }
            }
        }

        // segment epilogue: flush row denominators, protect A/B for next segment
        #pragma unroll
        for (int d = 0; d < 2; d++) {
            denom[d] += __shfl_xor_sync(0xffffffffu, denom[d], 1);
            denom[d] += __shfl_xor_sync(0xffffffffu, denom[d], 2);
        }
        if ((lane & 3) == 0) {
            #pragma unroll
            for (int d = 0; d < 2; d++)
                atomicAdd(&g_denom[row0 + d * 8 + (lane >> 2)], denom[d]);
        }
        denom[0] = denom[1] = 0.0f;
        __syncthreads();                     // all reads of A done before reload
    }

    // ======== last CTA: final log/mean reduction + counter reset ========
    __threadfence();
    __shared__ unsigned s_tick;
    if (tid == 0) s_tick = atomicAdd(&g_done, 1u);
    __syncthreads();
    if (s_tick == NUM_CTAS - 1) {
        float s = 0.0f;
        for (int r = tid; r < TWO_N; r += NTHREADS)
            s += logf(g_denom[r]) - g_pos[r & (NROWS - 1)] * 10.0f;
        #pragma unroll
        for (int o = 16; o; o >>= 1) s += __shfl_xor_sync(0xffffffffu, s, o);
        __shared__ float red[8];
        if (lane == 0) red[warp] = s;
        __syncthreads();
        if (tid == 0) {
            float v = 0.0f;
            #pragma unroll
            for (int w = 0; w < 8; w++) v += red[w];
            out[0] = v * (1.0f / (float)TWO_N);
            g_done = 0;                      // restore launch-invariant state
            g_sync = 0;                      // (all CTAs passed both counters)
        }
    }
}

// ---------------- launch ----------------------------------------------------
extern "C" void kernel_launch(void* const* d_in, const int* in_sizes, int n_in,
                              void* d_out, int out_size) {
    (void)in_sizes; (void)n_in; (void)out_size;
    const float* x1 = (const float*)d_in[0];
    const float* x2 = (const float*)d_in[1];
    float* out = (float*)d_out;

    cudaFuncSetAttribute(fused_kernel,
                         cudaFuncAttributeMaxDynamicSharedMemorySize, SMEM_TOTAL);

    fused_kernel<<<NUM_CTAS, NTHREADS, SMEM_TOTAL>>>(x1, x2, out);
}

// round 12
// speedup vs baseline: 1.1545x; 1.1020x over previous
#include <cuda_runtime.h>
#include <cuda_fp8.h>
#include <cstdint>

// ============================================================================
// ContrastiveLoss (N=4096, D=256, tau=0.1)
//   z = normalize(concat(x1,x2)) * sqrt(10*log2(e)) -> e4m3   (scale folded in)
//   acc = z'_r . z'_j = 14.427 * sim  ->  exp(sim/tau) = ex2(acc)
//   denom[r] = sum_j exp(...)  (diag -> exp(0)=1);  pos in exact fp32
// ROUND 12: 128x64 CTA tiles, 32x32 warp tiles (4Mx2N warps) — halves
// barrier count and cuts LDSM/MMA from 0.75 to 0.5 vs round 9, keeping
// the ring-3 / one-barrier-per-tile loop and lean split epilogue.
// ============================================================================

static constexpr int NROWS = 4096;
static constexpr int TWO_N = 8192;
static constexpr int D     = 256;          // K
static constexpr int BM    = 128;          // rows per strip
static constexpr int BN    = 64;           // cols per tile
// tiles (I strip, J 64-col block) with J >= 2I; pair(p, 63-p) -> 130 tiles.
static constexpr int NUM_TILES = 4160;
static constexpr int NUM_CTAS  = 296;                // 2 per SM
static constexpr int K_STEPS   = D / 32;             // 8 (fp8 k=32 per mma)
static constexpr int NTHREADS  = 256;

// sqrt(10 * log2(e)) — folded into z so epilogue is a bare ex2
#define ZSCALE 3.79828214f

// SMEM: padded row stride 272 B (17 x 16B)
static constexpr int TSTRIDE_B = 272;
static constexpr int A_TILE_BYTES = BM * TSTRIDE_B;   // 34816
static constexpr int B_TILE_BYTES = BN * TSTRIDE_B;   // 17408
static constexpr int SMEM_TOTAL = A_TILE_BYTES + 3 * B_TILE_BYTES;  // 87040

// ---------------- device scratch (allocation-free) --------------------------
__device__ unsigned char g_z8[TWO_N * D];   // e4m3 (pre-scaled), [8192][256]
__device__ float    g_pos[NROWS];
__device__ float    g_denom[TWO_N];
__device__ unsigned g_done;

// ---------------- PTX helpers ----------------------------------------------
__device__ __forceinline__ uint32_t smem_to_u32(const void* p) {
    uint32_t a;
    asm("{ .reg .u64 t; cvta.to.shared.u64 t, %1; cvt.u32.u64 %0, t; }"
        : "=r"(a) : "l"(p));
    return a;
}

__device__ __forceinline__ void cp_async16(uint32_t dst, const void* src) {
    asm volatile("cp.async.cg.shared.global [%0], [%1], 16;"
                 :: "r"(dst), "l"(src) : "memory");
}
#define CP_COMMIT() asm volatile("cp.async.commit_group;" ::: "memory")
#define CP_WAIT1()  asm volatile("cp.async.wait_group 1;" ::: "memory")

__device__ __forceinline__ void ldsm_x4(uint32_t* r, uint32_t addr) {
    asm volatile("ldmatrix.sync.aligned.m8n8.x4.shared.b16 {%0,%1,%2,%3}, [%4];"
                 : "=r"(r[0]), "=r"(r[1]), "=r"(r[2]), "=r"(r[3]) : "r"(addr));
}

#define MMA16832F8(d, a, bx, by) \
    asm volatile( \
        "mma.sync.aligned.m16n8k32.row.col.f32.e4m3.e4m3.f32 " \
        "{%0,%1,%2,%3}, {%4,%5,%6,%7}, {%8,%9}, {%0,%1,%2,%3};" \
        : "+f"((d)[0]), "+f"((d)[1]), "+f"((d)[2]), "+f"((d)[3]) \
        : "r"((a)[0]), "r"((a)[1]), "r"((a)[2]), "r"((a)[3]), \
          "r"(bx), "r"(by))

__device__ __forceinline__ float ex2f(float x) {
    float r;
    asm("ex2.approx.ftz.f32 %0, %1;" : "=f"(r) : "f"(x));
    return r;
}

__device__ __forceinline__ uint32_t pack_e4m3x4(float v0, float v1, float v2, float v3) {
    __nv_fp8x2_storage_t lo =
        __nv_cvt_float2_to_fp8x2(make_float2(v0, v1), __NV_SATFINITE, __NV_E4M3);
    __nv_fp8x2_storage_t hi =
        __nv_cvt_float2_to_fp8x2(make_float2(v2, v3), __NV_SATFINITE, __NV_E4M3);
    return (uint32_t)lo | ((uint32_t)hi << 16);
}

// ---------------- Stage 1: fused normalize + pos (reads x1/x2 once) --------
__global__ void normpos_kernel(const float* __restrict__ x1, const float* __restrict__ x2) {
    int i    = blockIdx.x * 8 + (threadIdx.x >> 5);   // pair row 0..4095
    int lane = threadIdx.x & 31;
    if (blockIdx.x == 0 && threadIdx.x == 0) g_done = 0;

    const float4* s1 = reinterpret_cast<const float4*>(x1 + (size_t)i * D);
    const float4* s2 = reinterpret_cast<const float4*>(x2 + (size_t)i * D);
    float4 a0 = s1[lane * 2], a1 = s1[lane * 2 + 1];
    float4 b0 = s2[lane * 2], b1 = s2[lane * 2 + 1];

    float ss1 = a0.x * a0.x + a0.y * a0.y + a0.z * a0.z + a0.w * a0.w
              + a1.x * a1.x + a1.y * a1.y + a1.z * a1.z + a1.w * a1.w;
    float ss2 = b0.x * b0.x + b0.y * b0.y + b0.z * b0.z + b0.w * b0.w
              + b1.x * b1.x + b1.y * b1.y + b1.z * b1.z + b1.w * b1.w;
    float dot = a0.x * b0.x + a0.y * b0.y + a0.z * b0.z + a0.w * b0.w
              + a1.x * b1.x + a1.y * b1.y + a1.z * b1.z + a1.w * b1.w;
    #pragma unroll
    for (int o = 16; o; o >>= 1) {
        ss1 += __shfl_xor_sync(0xffffffffu, ss1, o);
        ss2 += __shfl_xor_sync(0xffffffffu, ss2, o);
        dot += __shfl_xor_sync(0xffffffffu, dot, o);
    }
    float inv1 = 1.0f / fmaxf(sqrtf(ss1), 1e-12f);
    float inv2 = 1.0f / fmaxf(sqrtf(ss2), 1e-12f);
    if (lane == 0) {
        g_pos[i] = dot * inv1 * inv2;     // exact fp32, unscaled
        g_denom[i] = 0.0f;
        g_denom[i + NROWS] = 0.0f;
    }
    float q1 = inv1 * ZSCALE, q2 = inv2 * ZSCALE;

    uint2 w1, w2;
    w1.x = pack_e4m3x4(a0.x * q1, a0.y * q1, a0.z * q1, a0.w * q1);
    w1.y = pack_e4m3x4(a1.x * q1, a1.y * q1, a1.z * q1, a1.w * q1);
    w2.x = pack_e4m3x4(b0.x * q2, b0.y * q2, b0.z * q2, b0.w * q2);
    w2.y = pack_e4m3x4(b1.x * q2, b1.y * q2, b1.z * q2, b1.w * q2);
    *reinterpret_cast<uint2*>(g_z8 + (size_t)i * D + lane * 8) = w1;
    *reinterpret_cast<uint2*>(g_z8 + (size_t)(i + NROWS) * D + lane * 8) = w2;
}

// ---------------- tile loaders (fp8 rows of 256 B) ---------------------------
__device__ __forceinline__ void load_A(uint32_t dst, int row0, int tid) {
    const unsigned char* src = g_z8 + (size_t)row0 * D;
    #pragma unroll
    for (int i = 0; i < 8; i++) {
        int idx = tid + i * NTHREADS;      // 2048 chunks of 16B
        int r = idx >> 4, s = idx & 15;
        cp_async16(dst + r * TSTRIDE_B + s * 16, src + r * D + s * 16);
    }
}
__device__ __forceinline__ void load_B(uint32_t dst, int row0, int tid) {
    const unsigned char* src = g_z8 + (size_t)row0 * D;
    #pragma unroll
    for (int i = 0; i < 4; i++) {
        int idx = tid + i * NTHREADS;      // 1024 chunks of 16B
        int r = idx >> 4, s = idx & 15;
        cp_async16(dst + r * TSTRIDE_B + s * 16, src + r * D + s * 16);
    }
}

// ---------------- Stage 2: triangular fused FP8 GEMM + ex2 + sums -----------
__global__ __launch_bounds__(NTHREADS, 2)
void gemm_kernel(float* __restrict__ out) {
    extern __shared__ char smem[];
    const int tid  = threadIdx.x;
    const int lane = tid & 31;
    const int warp = tid >> 5;              // 0..7
    const int wm   = warp >> 1;             // 0..3  rows wm*32..+32
    const int wn   = warp & 1;              // 0..1  cols wn*32..+32
    const int cta  = blockIdx.x;

    const uint32_t smem_u = smem_to_u32(smem);
    const uint32_t A_base = smem_u;
    const uint32_t Bb0 = smem_u + A_TILE_BYTES;

    const int t0 = (int)(((long long)cta * NUM_TILES) / NUM_CTAS);
    const int t1 = (int)(((long long)(cta + 1) * NUM_TILES) / NUM_CTAS);

    const uint32_t a_off = (uint32_t)((wm * 32 + (lane & 15)) * TSTRIDE_B
                                      + (lane >> 4) * 16);
    const uint32_t b_off = (uint32_t)((wn * 32 + (lane & 15)) * TSTRIDE_B
                                      + (lane >> 4) * 16);

    float denom[4] = {0, 0, 0, 0};  // rows wm*32 + (d>>1)*16 + (d&1)*8 + lane>>2

    int t = t0;
    while (t < t1) {
        // decode segment: contiguous run of tiles sharing strip I
        int p   = t / 130;
        int idx = t - p * 130;
        int na  = 128 - 2 * p;
        int I, J, seg_end;
        if (idx < na) { I = p;      J = 2 * p + idx;             seg_end = 130 * p + na; }
        else          { I = 63 - p; J = 126 - 2 * p + (idx - na); seg_end = 130 * (p + 1); }
        const int te = (seg_end < t1) ? seg_end : t1;

        // segment prologue: A strip + first B tile (one group)
        load_A(A_base, I * BM, tid);
        load_B(Bb0 + (t % 3) * B_TILE_BYTES, J * BN, tid);
        CP_COMMIT();

        const int row0 = I * BM + wm * 32;

        for (; t < te; t++, J++) {
            if (t + 1 < te)
                load_B(Bb0 + ((t + 1) % 3) * B_TILE_BYTES, (J + 1) * BN, tid);
            CP_COMMIT();                     // possibly empty group
            CP_WAIT1();                      // retire group for tile t (and A)
            __syncthreads();                 // single barrier per tile

            const uint32_t Ab = A_base + a_off;
            const uint32_t Bb = Bb0 + (t % 3) * B_TILE_BYTES + b_off;

            float acc[2][4][4];
            #pragma unroll
            for (int mi = 0; mi < 2; mi++)
                #pragma unroll
                for (int ni = 0; ni < 4; ni++)
                    #pragma unroll
                    for (int e = 0; e < 4; e++) acc[mi][ni][e] = 0.0f;

            #pragma unroll
            for (int ks = 0; ks < K_STEPS; ks++) {
                uint32_t a0[4], a1[4], b01[4], b23[4];
                ldsm_x4(a0,  Ab + ks * 32);
                ldsm_x4(a1,  Ab + 16 * TSTRIDE_B + ks * 32);
                ldsm_x4(b01, Bb + ks * 32);
                ldsm_x4(b23, Bb + 16 * TSTRIDE_B + ks * 32);
                MMA16832F8(acc[0][0], a0, b01[0], b01[2]);
                MMA16832F8(acc[0][1], a0, b01[1], b01[3]);
                MMA16832F8(acc[0][2], a0, b23[0], b23[2]);
                MMA16832F8(acc[0][3], a0, b23[1], b23[3]);
                MMA16832F8(acc[1][0], a1, b01[0], b01[2]);
                MMA16832F8(acc[1][1], a1, b01[1], b01[3]);
                MMA16832F8(acc[1][2], a1, b23[0], b23[2]);
                MMA16832F8(acc[1][3], a1, b23[1], b23[3]);
            }

            // epilogue: v = ex2(acc) = exp(sim/tau)
            const int col0 = J * BN + wn * 32;
            if ((J >> 1) == I) {             // diagonal block: row sums only
                #pragma unroll
                for (int mi = 0; mi < 2; mi++)
                    #pragma unroll
                    for (int ni = 0; ni < 4; ni++)
                        #pragma unroll
                        for (int e = 0; e < 4; e++) {
                            float v = ex2f(acc[mi][ni][e]);
                            int r = row0 + mi * 16 + (e >> 1) * 8 + (lane >> 2);
                            int c = col0 + ni * 8 + (lane & 3) * 2 + (e & 1);
                            if (c == r) v = 1.0f;        // diag -> exp(0)
                            denom[mi * 2 + (e >> 1)] += v;
                        }
            } else {                         // off-diag: row sums + col sums
                float cs[8];
                #pragma unroll
                for (int ni = 0; ni < 4; ni++) {
                    float v00 = ex2f(acc[0][ni][0]);
                    float v01 = ex2f(acc[0][ni][1]);
                    float v02 = ex2f(acc[0][ni][2]);
                    float v03 = ex2f(acc[0][ni][3]);
                    float v10 = ex2f(acc[1][ni][0]);
                    float v11 = ex2f(acc[1][ni][1]);
                    float v12 = ex2f(acc[1][ni][2]);
                    float v13 = ex2f(acc[1][ni][3]);
                    denom[0] += v00 + v01;
                    denom[1] += v02 + v03;
                    denom[2] += v10 + v11;
                    denom[3] += v12 + v13;
                    cs[ni * 2]     = (v00 + v02) + (v10 + v12);
                    cs[ni * 2 + 1] = (v01 + v03) + (v11 + v13);
                }
                // reduce over row-carrying lane bits (2,3,4)
                #pragma unroll
                for (int k = 0; k < 8; k++) {
                    float x = cs[k];
                    x += __shfl_xor_sync(0xffffffffu, x, 4);
                    x += __shfl_xor_sync(0xffffffffu, x, 8);
                    x += __shfl_xor_sync(0xffffffffu, x, 16);
                    cs[k] = x;
                }
                if (lane < 4) {
                    #pragma unroll
                    for (int k = 0; k < 8; k++)
                        atomicAdd(&g_denom[col0 + (k >> 1) * 8 + lane * 2 + (k & 1)],
                                  cs[k]);
                }
            }
        }

        // segment epilogue: flush row denominators, protect A/B for next segment
        #pragma unroll
        for (int d = 0; d < 4; d++) {
            denom[d] += __shfl_xor_sync(0xffffffffu, denom[d], 1);
            denom[d] += __shfl_xor_sync(0xffffffffu, denom[d], 2);
        }
        if ((lane & 3) == 0) {
            #pragma unroll
            for (int d = 0; d < 4; d++)
                atomicAdd(&g_denom[row0 + (d >> 1) * 16 + (d & 1) * 8 + (lane >> 2)],
                          denom[d]);
        }
        #pragma unroll
        for (int d = 0; d < 4; d++) denom[d] = 0.0f;
        __syncthreads();                     // all reads of A done before reload
    }

    // ---- last CTA: final log/mean reduction ----
    __threadfence();
    __shared__ unsigned s_tick;
    if (tid == 0) s_tick = atomicAdd(&g_done, 1u);
    __syncthreads();
    if (s_tick == NUM_CTAS - 1) {
        float s = 0.0f;
        for (int r = tid; r < TWO_N; r += NTHREADS)
            s += logf(g_denom[r]) - g_pos[r & (NROWS - 1)] * 10.0f;
        #pragma unroll
        for (int o = 16; o; o >>= 1) s += __shfl_xor_sync(0xffffffffu, s, o);
        __shared__ float red[8];
        if (lane == 0) red[warp] = s;
        __syncthreads();
        if (tid == 0) {
            float v = 0.0f;
            #pragma unroll
            for (int w = 0; w < 8; w++) v += red[w];
            out[0] = v * (1.0f / (float)TWO_N);
        }
    }
}

// ---------------- launch ----------------------------------------------------
extern "C" void kernel_launch(void* const* d_in, const int* in_sizes, int n_in,
                              void* d_out, int out_size) {
    (void)in_sizes; (void)n_in; (void)out_size;
    const float* x1 = (const float*)d_in[0];
    const float* x2 = (const float*)d_in[1];
    float* out = (float*)d_out;

    cudaFuncSetAttribute(gemm_kernel,
                         cudaFuncAttributeMaxDynamicSharedMemorySize, SMEM_TOTAL);

    normpos_kernel<<<NROWS / 8, 256>>>(x1, x2);
    gemm_kernel<<<NUM_CTAS, NTHREADS, SMEM_TOTAL>>>(out);
}